// round 15
// baseline (speedup 1.0000x reference)
#include <cuda_runtime.h>
#include <cuda_bf16.h>

// ---------------------------------------------------------------------------
// Problem constants
// ---------------------------------------------------------------------------
#define BB    128
#define PP    49
#define TT    20
#define NSTEP 19
#define HD    512
#define ENCD  2048
#define VOC   20000
#define MROWS (BB*PP)                      // 6272
#define MACT_PAD (38*64)                   // 2432 = BB*NSTEP
#define PRED_ELEMS (128LL*19LL*20000LL)
#define KS_VG 8
#define PBLK  148                          // persistent blocks (<= SM count)

// ---------------------------------------------------------------------------
// Scratch (static device memory; referenced ONLY from device code)
// ---------------------------------------------------------------------------
__device__ __align__(128) float g_V   [MROWS*HD];
__device__ __align__(128) float g_WV  [MROWS*HD];
__device__ __align__(128) float g_Wpack[2560*1536];    // [W_ih|W_hh ; Wx|Wph]
__device__ __align__(128) float g_bpack[2560];
__device__ __align__(128) float g_GX  [BB*NSTEP*2560]; // x-part of gates, all t
__device__ __align__(128) float g_CH  [NSTEP*BB*HD];
__device__ __align__(128) float g_Gp  [2*BB*2560];     // gates partials (KS=2)
__device__ __align__(128) float g_H   [BB*HD];
__device__ __align__(128) float g_M   [BB*HD];
__device__ __align__(128) float g_HN  [BB*HD];
__device__ __align__(128) float g_S   [BB*HD];
__device__ __align__(128) float g_WhWsP[4*2*BB*HD];    // Wh/Ws partials (KS=4)
__device__ __align__(128) float g_vg  [BB*HD];
__device__ __align__(128) float g_vgP [KS_VG*BB*HD];
__device__ int g_sortind[BB];
__device__ int g_declen [BB];
__device__ int g_cnt    [NSTEP];
__device__ int g_capss  [BB*TT];
__device__ int g_rowmap [MACT_PAD];
__device__ int g_nact;
__device__ int g_barC;                                  // grid-barrier counter

// ---------------------------------------------------------------------------
// f32x2 helpers
// ---------------------------------------------------------------------------
__device__ __forceinline__ void ffma2(unsigned long long& d,
                                      unsigned long long a, unsigned long long b) {
    asm("fma.rn.f32x2 %0, %1, %2, %0;" : "+l"(d) : "l"(a), "l"(b));
}
__device__ __forceinline__ float2 upk2(unsigned long long v) {
    float2 r;
    asm("mov.b64 {%0,%1}, %2;" : "=f"(r.x), "=f"(r.y) : "l"(v));
    return r;
}
__device__ __forceinline__ void subbar(int nb) {
    asm volatile("bar.sync %0, %1;" :: "r"(nb), "r"(128) : "memory");
}

// ===========================================================================
// BIG GEMM: 128x64 tile, 128 threads, 8x8 microtile, double-buffered,
// conflict-free duplicated-B layout (8 groups x 20-float slots).
// ===========================================================================
enum { B_V = 0, B_WV = 1, B_GXB = 2, B_FINAL = 3 };

template<int MODE>
__global__ __launch_bounds__(128)
void sgemm_big(const float* __restrict__ A,
               const float* __restrict__ Bm,
               const float* __restrict__ bias,
               float* __restrict__ Cout,
               int N, int K)
{
    __shared__ __align__(16) float As [2][16][132];
    __shared__ __align__(16) float Bsd[2][16][164];

    const int tid = threadIdx.x;
    const int n0  = blockIdx.x * 64;
    const int m0  = blockIdx.y * 128;

    int nact = 0;
    if (MODE == B_FINAL) { nact = g_nact; if (m0 >= nact) return; }
    if (MODE == B_GXB)   { Bm = g_Wpack; bias = g_bpack; }
    const int ldb = (MODE == B_GXB) ? 1536 : ((MODE == B_V) ? ENCD : HD);

    const float* arow [4];
    const float* arow2[4];
    int rowi[4], kci[4];
    #pragma unroll
    for (int it = 0; it < 4; it++) {
        int s   = tid + it * 128;
        int row = s >> 2;
        rowi[it] = row;
        kci [it] = (s & 3) << 2;
        int gm = m0 + row;
        if (MODE == B_V) {
            int gr = g_sortind[gm / PP] * PP + gm % PP;
            arow[it] = A + (size_t)gr * ENCD;
        } else if (MODE == B_WV) {
            arow[it] = g_V + (size_t)gm * HD;
        } else if (MODE == B_FINAL) {
            arow[it] = g_CH + (size_t)g_rowmap[gm] * HD;
        } else {
            int b  = gm / NSTEP;
            int ts = gm - b * NSTEP;
            arow [it] = A + (size_t)g_capss[b * TT + ts] * HD;
            arow2[it] = g_vg + (size_t)b * HD;
        }
    }
    const float* brow[2];
    int bc[2], bkci[2];
    bool bok[2];
    #pragma unroll
    for (int it = 0; it < 2; it++) {
        int s  = tid + it * 128;
        int c  = s >> 2;
        bc  [it] = c;
        bkci[it] = (s & 3) << 2;
        int gn = n0 + c;
        bok [it] = (gn < N);
        brow[it] = Bm + (size_t)(bok[it] ? gn : 0) * ldb;
    }

    float4 aR[4], bR[2];

    #define BLOAD_TILE(k0)                                                    \
        {                                                                     \
            _Pragma("unroll")                                                 \
            for (int it = 0; it < 4; it++) {                                  \
                int gk = (k0) + kci[it];                                      \
                if (MODE == B_GXB) {                                          \
                    aR[it] = (gk < HD) ? *(const float4*)&arow[it][gk]        \
                                       : *(const float4*)&arow2[it][gk - HD]; \
                } else {                                                      \
                    aR[it] = *(const float4*)&arow[it][gk];                   \
                }                                                             \
            }                                                                 \
            _Pragma("unroll")                                                 \
            for (int it = 0; it < 2; it++) {                                  \
                bR[it] = bok[it] ? *(const float4*)&brow[it][(k0) + bkci[it]] \
                                 : make_float4(0.f, 0.f, 0.f, 0.f);           \
            }                                                                 \
        }

    #define BSTORE_TILE(buf)                                                  \
        {                                                                     \
            _Pragma("unroll")                                                 \
            for (int it = 0; it < 4; it++) {                                  \
                int kc = kci[it], row = rowi[it];                             \
                As[buf][kc + 0][row] = aR[it].x;                              \
                As[buf][kc + 1][row] = aR[it].y;                              \
                As[buf][kc + 2][row] = aR[it].z;                              \
                As[buf][kc + 3][row] = aR[it].w;                              \
            }                                                                 \
            _Pragma("unroll")                                                 \
            for (int it = 0; it < 2; it++) {                                  \
                int kc = bkci[it];                                            \
                int go = (bc[it] >> 3) * 20 + (bc[it] & 7) * 2;               \
                *(float2*)&Bsd[buf][kc + 0][go] = make_float2(bR[it].x, bR[it].x); \
                *(float2*)&Bsd[buf][kc + 1][go] = make_float2(bR[it].y, bR[it].y); \
                *(float2*)&Bsd[buf][kc + 2][go] = make_float2(bR[it].z, bR[it].z); \
                *(float2*)&Bsd[buf][kc + 3][go] = make_float2(bR[it].w, bR[it].w); \
            }                                                                 \
        }

    #define BLDFRAG(buf, k, aA, aB, b0, b1, b2, b3)                           \
        {                                                                     \
            const ulonglong2* ap = (const ulonglong2*)&As[buf][k][ty << 3];   \
            aA = ap[0]; aB = ap[1];                                           \
            const float* bbase = &Bsd[buf][k][tx * 20];                       \
            b0 = *(const ulonglong2*)(bbase + 0);                             \
            b1 = *(const ulonglong2*)(bbase + 4);                             \
            b2 = *(const ulonglong2*)(bbase + 8);                             \
            b3 = *(const ulonglong2*)(bbase + 12);                            \
        }

    unsigned long long acc[4][8];
    #pragma unroll
    for (int i = 0; i < 4; i++)
        #pragma unroll
        for (int j = 0; j < 8; j++) acc[i][j] = 0ull;

    const int ty = tid >> 3;
    const int tx = tid & 7;

    BLOAD_TILE(0);
    BSTORE_TILE(0);
    __syncthreads();
    int buf = 0;
    const int KT = K >> 4;
    for (int kt = 0; kt < KT; kt++) {
        if (kt + 1 < KT) BLOAD_TILE((kt + 1) << 4);
        ulonglong2 aAc, aBc, aAn, aBn;
        ulonglong2 b0c, b1c, b2c, b3c, b0n, b1n, b2n, b3n;
        BLDFRAG(buf, 0, aAc, aBc, b0c, b1c, b2c, b3c);
        #pragma unroll
        for (int k = 0; k < 16; k++) {
            if (k < 15) BLDFRAG(buf, k + 1, aAn, aBn, b0n, b1n, b2n, b3n);
            ffma2(acc[0][0], aAc.x, b0c.x); ffma2(acc[0][1], aAc.x, b0c.y);
            ffma2(acc[0][2], aAc.x, b1c.x); ffma2(acc[0][3], aAc.x, b1c.y);
            ffma2(acc[0][4], aAc.x, b2c.x); ffma2(acc[0][5], aAc.x, b2c.y);
            ffma2(acc[0][6], aAc.x, b3c.x); ffma2(acc[0][7], aAc.x, b3c.y);
            ffma2(acc[1][0], aAc.y, b0c.x); ffma2(acc[1][1], aAc.y, b0c.y);
            ffma2(acc[1][2], aAc.y, b1c.x); ffma2(acc[1][3], aAc.y, b1c.y);
            ffma2(acc[1][4], aAc.y, b2c.x); ffma2(acc[1][5], aAc.y, b2c.y);
            ffma2(acc[1][6], aAc.y, b3c.x); ffma2(acc[1][7], aAc.y, b3c.y);
            ffma2(acc[2][0], aBc.x, b0c.x); ffma2(acc[2][1], aBc.x, b0c.y);
            ffma2(acc[2][2], aBc.x, b1c.x); ffma2(acc[2][3], aBc.x, b1c.y);
            ffma2(acc[2][4], aBc.x, b2c.x); ffma2(acc[2][5], aBc.x, b2c.y);
            ffma2(acc[2][6], aBc.x, b3c.x); ffma2(acc[2][7], aBc.x, b3c.y);
            ffma2(acc[3][0], aBc.y, b0c.x); ffma2(acc[3][1], aBc.y, b0c.y);
            ffma2(acc[3][2], aBc.y, b1c.x); ffma2(acc[3][3], aBc.y, b1c.y);
            ffma2(acc[3][4], aBc.y, b2c.x); ffma2(acc[3][5], aBc.y, b2c.y);
            ffma2(acc[3][6], aBc.y, b3c.x); ffma2(acc[3][7], aBc.y, b3c.y);
            if (k < 15) {
                aAc = aAn; aBc = aBn;
                b0c = b0n; b1c = b1n; b2c = b2n; b3c = b3n;
            }
        }
        if (kt + 1 < KT) {
            BSTORE_TILE(buf ^ 1);
            __syncthreads();
            buf ^= 1;
        }
    }
    #undef BLOAD_TILE
    #undef BSTORE_TILE
    #undef BLDFRAG

    float* Cp;
    int ldc;
    if      (MODE == B_V)   { Cp = g_V;  ldc = HD; }
    else if (MODE == B_WV)  { Cp = g_WV; ldc = HD; }
    else if (MODE == B_GXB) { Cp = g_GX; ldc = 2560; }
    else                    { Cp = Cout; ldc = N; }

    const int nb = n0 + (tx << 3);
    float bs[8];
    #pragma unroll
    for (int j = 0; j < 8; j++)
        bs[j] = (nb + j < N) ? bias[nb + j] : 0.f;

    #pragma unroll
    for (int i = 0; i < 4; i++) {
        #pragma unroll
        for (int half = 0; half < 2; half++) {
            int r  = (ty << 3) + (i << 1) + half;
            int i0 = m0 + r;
            float vals[8];
            #pragma unroll
            for (int j = 0; j < 8; j++) {
                float2 v = upk2(acc[i][j]);
                float x = (half ? v.y : v.x) + bs[j];
                if (MODE == B_V) x = fmaxf(x, 0.f);
                vals[j] = x;
            }
            if (MODE == B_FINAL) {
                if (i0 < nact) {
                    int rm = g_rowmap[i0];
                    int b = rm & 127, ts = rm >> 7;
                    float* dst = Cp + ((size_t)(b * NSTEP + ts)) * N + nb;
                    if (nb + 7 < N) {
                        *(float4*)(dst)     = make_float4(vals[0], vals[1], vals[2], vals[3]);
                        *(float4*)(dst + 4) = make_float4(vals[4], vals[5], vals[6], vals[7]);
                    } else {
                        #pragma unroll
                        for (int j = 0; j < 8; j++)
                            if (nb + j < N) dst[j] = vals[j];
                    }
                }
            } else {
                float* dst = Cp + (size_t)i0 * ldc + nb;
                *(float4*)(dst)     = make_float4(vals[0], vals[1], vals[2], vals[3]);
                *(float4*)(dst + 4) = make_float4(vals[4], vals[5], vals[6], vals[7]);
            }
        }
    }
}

// ===========================================================================
// vg small GEMM (split-K, standalone; runs once in setup)
// ===========================================================================
__global__ __launch_bounds__(128)
void sgemm_vg(const float* __restrict__ A, const float* __restrict__ Bm, int K)
{
    __shared__ __align__(16) float As [2][16][68];
    __shared__ __align__(16) float Bsd[2][16][132];

    const int tid = threadIdx.x;
    const int n0  = blockIdx.x * 64;
    const int m0C = blockIdx.y * 64;
    const int kz  = blockIdx.z;

    const float* arow[2];
    int rowi[2], kci[2];
    #pragma unroll
    for (int it = 0; it < 2; it++) {
        int s   = tid + it * 128;
        int row = s >> 2;
        rowi[it] = row;
        kci [it] = (s & 3) << 2;
        arow[it] = A + (size_t)g_sortind[m0C + row] * ENCD + kz * K;
    }
    const float* brow[2];
    int bn[2], bkci[2];
    #pragma unroll
    for (int it = 0; it < 2; it++) {
        int s  = tid + it * 128;
        int nr = s >> 2;
        bn  [it] = nr;
        bkci[it] = (s & 3) << 2;
        brow[it] = Bm + (size_t)(n0 + nr) * ENCD + kz * K;
    }

    float4 aR[2], bR[2];

    #define LOAD_TILE(k0)                                                     \
        {                                                                     \
            _Pragma("unroll")                                                 \
            for (int it = 0; it < 2; it++)                                    \
                aR[it] = *(const float4*)&arow[it][(k0) + kci[it]];           \
            _Pragma("unroll")                                                 \
            for (int it = 0; it < 2; it++)                                    \
                bR[it] = *(const float4*)&brow[it][(k0) + bkci[it]];          \
        }
    #define STORE_TILE(buf)                                                   \
        {                                                                     \
            _Pragma("unroll")                                                 \
            for (int it = 0; it < 2; it++) {                                  \
                int kc = kci[it], row = rowi[it];                             \
                As[buf][kc + 0][row] = aR[it].x;                              \
                As[buf][kc + 1][row] = aR[it].y;                              \
                As[buf][kc + 2][row] = aR[it].z;                              \
                As[buf][kc + 3][row] = aR[it].w;                              \
            }                                                                 \
            _Pragma("unroll")                                                 \
            for (int it = 0; it < 2; it++) {                                  \
                int kc = bkci[it], nr2 = bn[it] * 2;                          \
                *(float2*)&Bsd[buf][kc + 0][nr2] = make_float2(bR[it].x, bR[it].x); \
                *(float2*)&Bsd[buf][kc + 1][nr2] = make_float2(bR[it].y, bR[it].y); \
                *(float2*)&Bsd[buf][kc + 2][nr2] = make_float2(bR[it].z, bR[it].z); \
                *(float2*)&Bsd[buf][kc + 3][nr2] = make_float2(bR[it].w, bR[it].w); \
            }                                                                 \
        }
    #define LDFRAG(buf, k, aA, aB, b01, b23)                                  \
        {                                                                     \
            const ulonglong2* ap = (const ulonglong2*)&As[buf][k][ty << 3];   \
            aA = ap[0]; aB = ap[1];                                           \
            const ulonglong2* bp = (const ulonglong2*)&Bsd[buf][k][tx << 3];  \
            b01 = bp[0]; b23 = bp[1];                                         \
        }

    unsigned long long acc[4][4];
    #pragma unroll
    for (int i = 0; i < 4; i++)
        #pragma unroll
        for (int j = 0; j < 4; j++) acc[i][j] = 0ull;

    const int ty = tid >> 4;
    const int tx = tid & 15;

    LOAD_TILE(0);
    STORE_TILE(0);
    __syncthreads();
    int buf = 0;
    const int KT = K >> 4;
    for (int kt = 0; kt < KT; kt++) {
        if (kt + 1 < KT) LOAD_TILE((kt + 1) << 4);
        ulonglong2 aAc, aBc, b01c, b23c, aAn, aBn, b01n, b23n;
        LDFRAG(buf, 0, aAc, aBc, b01c, b23c);
        #pragma unroll
        for (int k = 0; k < 16; k++) {
            if (k < 15) LDFRAG(buf, k + 1, aAn, aBn, b01n, b23n);
            ffma2(acc[0][0], aAc.x, b01c.x); ffma2(acc[0][1], aAc.x, b01c.y);
            ffma2(acc[0][2], aAc.x, b23c.x); ffma2(acc[0][3], aAc.x, b23c.y);
            ffma2(acc[1][0], aAc.y, b01c.x); ffma2(acc[1][1], aAc.y, b01c.y);
            ffma2(acc[1][2], aAc.y, b23c.x); ffma2(acc[1][3], aAc.y, b23c.y);
            ffma2(acc[2][0], aBc.x, b01c.x); ffma2(acc[2][1], aBc.x, b01c.y);
            ffma2(acc[2][2], aBc.x, b23c.x); ffma2(acc[2][3], aBc.x, b23c.y);
            ffma2(acc[3][0], aBc.y, b01c.x); ffma2(acc[3][1], aBc.y, b01c.y);
            ffma2(acc[3][2], aBc.y, b23c.x); ffma2(acc[3][3], aBc.y, b23c.y);
            if (k < 15) { aAc = aAn; aBc = aBn; b01c = b01n; b23c = b23n; }
        }
        if (kt + 1 < KT) {
            STORE_TILE(buf ^ 1);
            __syncthreads();
            buf ^= 1;
        }
    }
    #undef LOAD_TILE
    #undef STORE_TILE
    #undef LDFRAG

    float* Cp = g_vgP + (size_t)kz * (BB * HD);
    #pragma unroll
    for (int j = 0; j < 4; j++) {
        int n = n0 + (tx << 2) + j;
        #pragma unroll
        for (int i2 = 0; i2 < 4; i2++) {
            float2 v = upk2(acc[i2][j]);
            int r0 = (ty << 3) + (i2 << 1);
            Cp[(size_t)(m0C + r0)     * HD + n] = v.x;
            Cp[(size_t)(m0C + r0 + 1) * HD + n] = v.y;
        }
    }
}

// ===========================================================================
// PERSISTENT STEP KERNEL — runs all 19 decode steps with software grid sync.
// 148 blocks x 256 threads; each block = two 128-thread sub-blocks.
// ===========================================================================
__device__ __forceinline__ void gsync(int phase) {
    __syncthreads();
    if (threadIdx.x == 0) {
        int target = phase * PBLK;
        int old;
        asm volatile("atom.release.gpu.add.s32 %0, [%1], 1;"
                     : "=r"(old) : "l"(&g_barC) : "memory");
        if (old + 1 < target) {
            int v;
            do {
                asm volatile("nanosleep.u32 64;");
                asm volatile("ld.acquire.gpu.b32 %0, [%1];"
                             : "=r"(v) : "l"(&g_barC) : "memory");
            } while (v < target);
        }
    }
    __syncthreads();
}

// 64x64xK GEMM tile, 128 threads (one sub-block), partial store (no bias).
__device__ void gemm64(int t128, int nbar,
                       const float* __restrict__ Abase, int lda,
                       const float* __restrict__ Bbase, int ldb, int K,
                       float* __restrict__ Cbase, int ldc,
                       float (*As)[16][68], float (*Bs)[16][132])
{
    const float* arow[2];
    const float* brow[2];
    int rowi[2], kci[2];
    #pragma unroll
    for (int it = 0; it < 2; it++) {
        int s   = t128 + it * 128;
        int row = s >> 2;
        rowi[it] = row;
        kci [it] = (s & 3) << 2;
        arow[it] = Abase + (size_t)row * lda;
        brow[it] = Bbase + (size_t)row * ldb;
    }
    float4 aR[2], bR[2];

    #define PLOAD(k0)                                                         \
        {                                                                     \
            _Pragma("unroll")                                                 \
            for (int it = 0; it < 2; it++) {                                  \
                aR[it] = *(const float4*)&arow[it][(k0) + kci[it]];           \
                bR[it] = *(const float4*)&brow[it][(k0) + kci[it]];           \
            }                                                                 \
        }
    #define PSTORE(buf)                                                       \
        {                                                                     \
            _Pragma("unroll")                                                 \
            for (int it = 0; it < 2; it++) {                                  \
                int kc = kci[it], row = rowi[it];                             \
                As[buf][kc + 0][row] = aR[it].x;                              \
                As[buf][kc + 1][row] = aR[it].y;                              \
                As[buf][kc + 2][row] = aR[it].z;                              \
                As[buf][kc + 3][row] = aR[it].w;                              \
                int nr2 = row * 2;                                            \
                *(float2*)&Bs[buf][kc + 0][nr2] = make_float2(bR[it].x, bR[it].x); \
                *(float2*)&Bs[buf][kc + 1][nr2] = make_float2(bR[it].y, bR[it].y); \
                *(float2*)&Bs[buf][kc + 2][nr2] = make_float2(bR[it].z, bR[it].z); \
                *(float2*)&Bs[buf][kc + 3][nr2] = make_float2(bR[it].w, bR[it].w); \
            }                                                                 \
        }
    #define PFRAG(buf, k, aA, aB, b01, b23)                                   \
        {                                                                     \
            const ulonglong2* ap = (const ulonglong2*)&As[buf][k][ty << 3];   \
            aA = ap[0]; aB = ap[1];                                           \
            const ulonglong2* bp = (const ulonglong2*)&Bs[buf][k][tx << 3];   \
            b01 = bp[0]; b23 = bp[1];                                         \
        }

    unsigned long long acc[4][4];
    #pragma unroll
    for (int i = 0; i < 4; i++)
        #pragma unroll
        for (int j = 0; j < 4; j++) acc[i][j] = 0ull;

    const int ty = t128 >> 4;
    const int tx = t128 & 15;

    PLOAD(0);
    PSTORE(0);
    subbar(nbar);
    int buf = 0;
    const int KT = K >> 4;
    for (int kt = 0; kt < KT; kt++) {
        if (kt + 1 < KT) PLOAD((kt + 1) << 4);
        ulonglong2 aAc, aBc, b01c, b23c, aAn, aBn, b01n, b23n;
        PFRAG(buf, 0, aAc, aBc, b01c, b23c);
        #pragma unroll
        for (int k = 0; k < 16; k++) {
            if (k < 15) PFRAG(buf, k + 1, aAn, aBn, b01n, b23n);
            ffma2(acc[0][0], aAc.x, b01c.x); ffma2(acc[0][1], aAc.x, b01c.y);
            ffma2(acc[0][2], aAc.x, b23c.x); ffma2(acc[0][3], aAc.x, b23c.y);
            ffma2(acc[1][0], aAc.y, b01c.x); ffma2(acc[1][1], aAc.y, b01c.y);
            ffma2(acc[1][2], aAc.y, b23c.x); ffma2(acc[1][3], aAc.y, b23c.y);
            ffma2(acc[2][0], aBc.x, b01c.x); ffma2(acc[2][1], aBc.x, b01c.y);
            ffma2(acc[2][2], aBc.x, b23c.x); ffma2(acc[2][3], aBc.x, b23c.y);
            ffma2(acc[3][0], aBc.y, b01c.x); ffma2(acc[3][1], aBc.y, b01c.y);
            ffma2(acc[3][2], aBc.y, b23c.x); ffma2(acc[3][3], aBc.y, b23c.y);
            if (k < 15) { aAc = aAn; aBc = aBn; b01c = b01n; b23c = b23n; }
        }
        if (kt + 1 < KT) {
            PSTORE(buf ^ 1);
            subbar(nbar);
            buf ^= 1;
        }
    }
    #undef PLOAD
    #undef PSTORE
    #undef PFRAG

    #pragma unroll
    for (int j = 0; j < 4; j++) {
        int n = (tx << 2) + j;
        #pragma unroll
        for (int i2 = 0; i2 < 4; i2++) {
            float2 v = upk2(acc[i2][j]);
            int r0 = (ty << 3) + (i2 << 1);
            Cbase[(size_t)r0       * ldc + n] = v.x;
            Cbase[(size_t)(r0 + 1) * ldc + n] = v.y;
        }
    }
}

__device__ __forceinline__ float sigm(float x) { return 1.0f / (1.0f + expf(-x)); }

// 128-thread attention for one batch row b at step t.
__device__ void attn_sub(int t128, int nbar, int t, int b,
                         const float* __restrict__ attbh, const float* __restrict__ attbs,
                         const float* __restrict__ wa,    const float* __restrict__ ba,
                         const float* __restrict__ wahat, const float* __restrict__ bahat,
                         float* sm)
{
    float* shWh = sm;
    float* shWs = sm + 512;
    float* zsh  = sm + 1024;
    float* alph = sm + 1088;
    // reduce HS partials + biases
    for (int e = t128; e < 512; e += 128) {
        float vh = attbh[e], vs = attbs[e];
        #pragma unroll
        for (int z = 0; z < 4; z++) {
            vh += g_WhWsP[(size_t)z * (2 * BB * HD) + (size_t)b * HD + e];
            vs += g_WhWsP[(size_t)z * (2 * BB * HD) + (size_t)(BB + b) * HD + e];
        }
        shWh[e] = vh;
        shWs[e] = vs;
    }
    subbar(nbar);

    int warp = (t128 >> 5), lane = t128 & 31;
    for (int idx = warp; idx < 50; idx += 4) {
        float sum = 0.f;
        if (idx < 49) {
            const float* wv = g_WV + ((size_t)(b * PP + idx)) * 512;
            #pragma unroll
            for (int e = lane; e < 512; e += 32)
                sum += tanhf(wv[e] + shWh[e]) * wa[e];
        } else {
            #pragma unroll
            for (int e = lane; e < 512; e += 32)
                sum += tanhf(shWs[e] + shWh[e]) * wahat[e];
        }
        #pragma unroll
        for (int o = 16; o; o >>= 1) sum += __shfl_down_sync(0xffffffffu, sum, o);
        if (lane == 0) zsh[idx] = sum + (idx < 49 ? ba[0] : bahat[0]);
    }
    subbar(nbar);

    if (warp == 0) {
        float z0 = (lane < 49)      ? zsh[lane]      : -1e30f;
        float z1 = (lane + 32 < 49) ? zsh[lane + 32] : -1e30f;
        float mx = fmaxf(z0, z1);
        #pragma unroll
        for (int o = 16; o; o >>= 1) mx = fmaxf(mx, __shfl_xor_sync(0xffffffffu, mx, o));
        float e0 = (lane < 49)      ? expf(z0 - mx) : 0.f;
        float e1 = (lane + 32 < 49) ? expf(z1 - mx) : 0.f;
        float smx = e0 + e1;
        #pragma unroll
        for (int o = 16; o; o >>= 1) smx += __shfl_xor_sync(0xffffffffu, smx, o);
        float inv = 1.f / smx;
        if (lane < 49)      alph[lane]      = e0 * inv;
        if (lane + 32 < 49) alph[lane + 32] = e1 * inv;
        if (lane == 0) {
            float zh = zsh[49];
            float m2 = fmaxf(mx, zh);
            float s2 = smx * expf(mx - m2) + expf(zh - m2);
            sm[1152] = expf(zh - m2) / s2;
        }
    }
    subbar(nbar);

    float beta = sm[1152];
    for (int e = t128; e < 512; e += 128) {
        float c = 0.f;
        const float* Vb = g_V + (size_t)b * PP * 512 + e;
        #pragma unroll 7
        for (int p = 0; p < PP; p++) c += alph[p] * Vb[p * 512];
        int idx = b * 512 + e;
        float ch = beta * g_S[idx] + (1.f - beta) * c + g_HN[idx];
        g_CH[((size_t)t * BB + b) * 512 + e] = ch;
    }
}

__global__ __launch_bounds__(256)
void step_persist(const float* __restrict__ attWh, const float* __restrict__ attbh,
                  const float* __restrict__ attWs, const float* __restrict__ attbs,
                  const float* __restrict__ wa,    const float* __restrict__ ba,
                  const float* __restrict__ wahat, const float* __restrict__ bahat)
{
    __shared__ __align__(16) float As[2][2][16][68];
    __shared__ __align__(16) float Bs[2][2][16][132];

    const int tid  = threadIdx.x;
    const int bid  = blockIdx.x;
    const int sub  = tid >> 7;
    const int t128 = tid & 127;
    const int nbar = sub + 1;
    int ph = 0;

    for (int t = 0; t < NSTEP; t++) {
        int cnt = g_cnt[t];
        int mt  = (cnt + 63) >> 6;       // 1 or 2 m-tiles

        // ---- P1: gates partials  G_p[kz] = h[:,kz*256:+256] @ Wpack2^T ----
        {
            int j = bid * 2 + sub;
            int njobs = 40 * mt * 2;
            if (j < njobs) {
                int ntile = j % 40;
                int r     = j / 40;
                int mtile = r % mt;
                int kz    = r / mt;
                gemm64(t128, nbar,
                       g_H + (size_t)(mtile * 64) * HD + kz * 256, HD,
                       g_Wpack + 1024 + kz * 256 + (size_t)(ntile * 64) * 1536, 1536,
                       256,
                       g_Gp + (size_t)kz * (BB * 2560)
                            + (size_t)(mtile * 64) * 2560 + ntile * 64, 2560,
                       As[sub], Bs[sub]);
            }
        }
        gsync(++ph);

        // ---- P2: LSTM elementwise (reduce 2 partials + GX) ----
        for (int idx = bid * 256 + tid; idx < cnt * 512; idx += PBLK * 256) {
            int b = idx >> 9, j = idx & 511;
            const float* GX = g_GX + ((size_t)b * NSTEP + t) * 2560;
            float ga[5];
            #pragma unroll
            for (int g5 = 0; g5 < 5; g5++) {
                int n = g5 * 512 + j;
                ga[g5] = GX[n] + g_Gp[(size_t)b * 2560 + n]
                               + g_Gp[(size_t)(BB + b) * 2560 + n];
            }
            float ig = sigm(ga[0]);
            float fg = sigm(ga[1]);
            float gg = tanhf(ga[2]);
            float og = sigm(ga[3]);
            float gt = sigm(ga[4]);
            float mn = fg * g_M[idx] + ig * gg;
            float tm = tanhf(mn);
            float hn = og * tm;
            g_HN[idx] = hn;
            g_S[idx]  = gt * tm;
            if (t < g_declen[b]) { g_H[idx] = hn; g_M[idx] = mn; }
        }
        gsync(++ph);

        // ---- P3: Wh/Ws partials (KS=4) ----
        {
            int j = bid * 2 + sub;       // 128 jobs
            if (j < 128) {
                int ntile = j & 7;
                int slot  = (j >> 3) & 3;   // 0,1=Wh m-tiles; 2,3=Ws m-tiles
                int kz    = j >> 5;
                if ((slot & 1) * 64 < cnt) {
                    const float* Ab = ((slot < 2) ? g_HN : g_S)
                                    + (size_t)((slot & 1) * 64) * HD + kz * 128;
                    const float* Bb = ((slot < 2) ? attWh : attWs)
                                    + (size_t)(ntile * 64) * HD + kz * 128;
                    float* Cb = g_WhWsP + (size_t)kz * (2 * BB * HD)
                              + (size_t)(((slot < 2) ? 0 : BB) + (slot & 1) * 64) * HD
                              + ntile * 64;
                    gemm64(t128, nbar, Ab, HD, Bb, HD, 128, Cb, HD, As[sub], Bs[sub]);
                }
            }
        }
        gsync(++ph);

        // ---- P4: attention + CH ----
        {
            int b = bid * 2 + sub;
            if (b < cnt)
                attn_sub(t128, nbar, t, b, attbh, attbs, wa, ba, wahat, bahat,
                         (float*)As[sub]);
        }
        gsync(++ph);
    }
}

// ---------------------------------------------------------------------------
// Prep: stable descending argsort, caps gather, cnt_t, compact rowmap, tails
// ---------------------------------------------------------------------------
__global__ void prep_kernel(const int* __restrict__ caplens,
                            const int* __restrict__ caps,
                            float* __restrict__ out, long long out_size)
{
    __shared__ int clsh[BB];
    __shared__ int off[NSTEP + 1];
    int b = threadIdx.x;
    int cl = caplens[b];
    clsh[b] = cl;
    __syncthreads();
    int rank = 0;
    #pragma unroll 8
    for (int j = 0; j < BB; j++) {
        int cj = clsh[j];
        if (cj > cl || (cj == cl && j < b)) rank++;
    }
    g_sortind[rank] = b;
    g_declen[rank]  = cl - 1;
    __syncthreads();

    int si = g_sortind[b];
    for (int t = 0; t < TT; t++) g_capss[b * TT + t] = caps[si * TT + t];

    if (b < NSTEP) {
        int c = 0;
        for (int j = 0; j < BB; j++) if (g_declen[j] > b) c++;
        g_cnt[b] = c;
    }
    __syncthreads();
    if (b == 0) {
        int o = 0;
        for (int t = 0; t < NSTEP; t++) { off[t] = o; o += g_cnt[t]; }
        off[NSTEP] = o;
        g_nact = o;
        g_barC = 0;
    }
    __syncthreads();
    for (int t = 0; t < NSTEP; t++)
        if (b < g_cnt[t]) g_rowmap[off[t] + b] = t * BB + b;
    __syncthreads();
    int nact = off[NSTEP];
    int lastrm = g_rowmap[nact - 1];
    for (int i = nact + b; i < MACT_PAD; i += BB) g_rowmap[i] = lastrm;

    for (int i = b; i < BB * HD; i += BB) { g_H[i] = 0.f; g_M[i] = 0.f; }

    if (out_size >= PRED_ELEMS + 2816LL) {
        for (int t = 0; t < TT; t++)
            out[PRED_ELEMS + b * TT + t] = (float)g_capss[b * TT + t];
        out[PRED_ELEMS + 2560 + b] = (float)g_declen[b];
        out[PRED_ELEMS + 2688 + b] = (float)g_sortind[b];
    }
}

// ---------------------------------------------------------------------------
// Pack LSTM + gate weights into one (2560 x 1536) NT weight + fused bias
// ---------------------------------------------------------------------------
__global__ void pack_weights(const float* __restrict__ Wih, const float* __restrict__ Whh,
                             const float* __restrict__ Wx,  const float* __restrict__ Wph,
                             const float* __restrict__ bih, const float* __restrict__ bhh,
                             const float* __restrict__ bx,  const float* __restrict__ bph)
{
    int i = blockIdx.x * blockDim.x + threadIdx.x;
    int n = i / 1536;
    int k = i - n * 1536;
    float v;
    if (n < 2048) v = (k < 1024) ? Wih[n * 1024 + k] : Whh[n * 512 + (k - 1024)];
    else {
        int n2 = n - 2048;
        v = (k < 1024) ? Wx[n2 * 1024 + k] : Wph[n2 * 512 + (k - 1024)];
    }
    g_Wpack[i] = v;
    if (i < 2560)
        g_bpack[i] = (i < 2048) ? (bih[i] + bhh[i]) : (bx[i - 2048] + bph[i - 2048]);
}

// ---------------------------------------------------------------------------
// vg split-K reduction + bias + relu
// ---------------------------------------------------------------------------
__global__ void vg_reduce(const float* __restrict__ bg)
{
    int i = blockIdx.x * 256 + threadIdx.x;
    float v = bg[i & 511];
    #pragma unroll
    for (int z = 0; z < KS_VG; z++) v += g_vgP[z * (BB * HD) + i];
    g_vg[i] = fmaxf(v, 0.f);
}

// ---------------------------------------------------------------------------
// Zero-fill predictions of inactive (b,t) rows
// ---------------------------------------------------------------------------
__global__ void zero_inactive(float* __restrict__ out)
{
    int bt = blockIdx.x;
    int b = bt / NSTEP, t = bt - b * NSTEP;
    if (t < g_declen[b]) return;
    float4* dst = (float4*)(out + (size_t)bt * VOC);
    for (int i = threadIdx.x; i < VOC / 4; i += blockDim.x)
        dst[i] = make_float4(0.f, 0.f, 0.f, 0.f);
}

// ---------------------------------------------------------------------------
// Host launcher — kernel launches only
// ---------------------------------------------------------------------------
extern "C" void kernel_launch(void* const* d_in, const int* in_sizes, int n_in,
                              void* d_out, int out_size)
{
    (void)in_sizes; (void)n_in;
    const float* enc    = (const float*)d_in[0];
    const float* gimg   = (const float*)d_in[1];
    const int*   caps   = (const int*)  d_in[2];
    const int*   caplens= (const int*)  d_in[3];
    const float* embW   = (const float*)d_in[4];
    const float* Wih    = (const float*)d_in[5];
    const float* Whh    = (const float*)d_in[6];
    const float* bih    = (const float*)d_in[7];
    const float* bhh    = (const float*)d_in[8];
    const float* Wg     = (const float*)d_in[9];
    const float* bg     = (const float*)d_in[10];
    const float* Wi     = (const float*)d_in[11];
    const float* bi     = (const float*)d_in[12];
    const float* Wx     = (const float*)d_in[13];
    const float* bx     = (const float*)d_in[14];
    const float* Wph    = (const float*)d_in[15];
    const float* bph    = (const float*)d_in[16];
    const float* attWh  = (const float*)d_in[17];
    const float* attbh  = (const float*)d_in[18];
    const float* attWs  = (const float*)d_in[19];
    const float* attbs  = (const float*)d_in[20];
    const float* attWV  = (const float*)d_in[21];
    const float* attbV  = (const float*)d_in[22];
    const float* wa     = (const float*)d_in[23];
    const float* ba     = (const float*)d_in[24];
    const float* wahat  = (const float*)d_in[25];
    const float* bahat  = (const float*)d_in[26];
    const float* finalW = (const float*)d_in[27];
    const float* finalb = (const float*)d_in[28];
    float* out = (float*)d_out;

    // --- setup ---
    prep_kernel<<<1, 128>>>(caplens, caps, out, (long long)out_size);
    pack_weights<<<(2560 * 1536) / 256, 256>>>(Wih, Whh, Wx, Wph, bih, bhh, bx, bph);
    zero_inactive<<<BB * NSTEP, 256>>>(out);

    // vg partials + reduce
    sgemm_vg<<<dim3(8, 2, KS_VG), 128>>>(gimg, Wg, ENCD / KS_VG);
    vg_reduce<<<BB * HD / 256, 256>>>(bg);
    // V = relu(enc_s @ Wi^T + bi)
    sgemm_big<B_V><<<dim3(8, MROWS / 128), 128>>>(enc, Wi, bi, nullptr, HD, ENCD);
    // GX = [emb_t | vg] @ Wpack[:, :1024]^T + bpack
    sgemm_big<B_GXB><<<dim3(40, MACT_PAD / 128), 128>>>(embW, nullptr, nullptr,
        nullptr, 2560, 1024);
    // WV = V @ att_WV^T + bV
    sgemm_big<B_WV><<<dim3(8, MROWS / 128), 128>>>(nullptr, attWV, attbV,
        nullptr, HD, HD);

    // --- all 19 decode steps in ONE persistent kernel ---
    step_persist<<<PBLK, 256>>>(attWh, attbh, attWs, attbs, wa, ba, wahat, bahat);

    // --- batched final projection over compacted active rows ---
    sgemm_big<B_FINAL><<<dim3((VOC + 63) / 64, MACT_PAD / 128), 128>>>(nullptr,
        finalW, finalb, out, VOC, HD);
}

// round 16
// speedup vs baseline: 1.2212x; 1.2212x over previous
#include <cuda_runtime.h>
#include <cuda_bf16.h>

// ---------------------------------------------------------------------------
// Problem constants
// ---------------------------------------------------------------------------
#define BB    128
#define PP    49
#define TT    20
#define NSTEP 19
#define HD    512
#define ENCD  2048
#define VOC   20000
#define MROWS (BB*PP)                      // 6272
#define MACT_PAD (38*64)                   // 2432 = BB*NSTEP
#define PRED_ELEMS (128LL*19LL*20000LL)
#define KS_G  4
#define KS_HS 4
#define KS_VG 8

// ---------------------------------------------------------------------------
// Scratch (static device memory; referenced ONLY from device code)
// ---------------------------------------------------------------------------
__device__ __align__(128) float g_V   [MROWS*HD];
__device__ __align__(128) float g_WV  [MROWS*HD];
__device__ __align__(128) float g_Wpack[2560*1536];    // [W_ih|W_hh ; Wx|Wph]
__device__ __align__(128) float g_bpack[2560];
__device__ __align__(128) float g_GX  [BB*NSTEP*2560]; // x-part of gates, all t
__device__ __align__(128) float g_CH  [NSTEP*BB*HD];
__device__ __align__(128) float g_Gp  [KS_G*BB*2560];
__device__ __align__(128) float g_H   [BB*HD];
__device__ __align__(128) float g_M   [BB*HD];
__device__ __align__(128) float g_HN  [BB*HD];
__device__ __align__(128) float g_S   [BB*HD];
__device__ __align__(128) float g_WhWsP[KS_HS*2*BB*HD];
__device__ __align__(128) float g_vg  [BB*HD];
__device__ __align__(128) float g_vgP [KS_VG*BB*HD];
__device__ int g_sortind[BB];
__device__ int g_declen [BB];
__device__ int g_cnt    [NSTEP];
__device__ int g_capss  [BB*TT];
__device__ int g_rowmap [MACT_PAD];
__device__ int g_nact;

// ---------------------------------------------------------------------------
// f32x2 helpers
// ---------------------------------------------------------------------------
__device__ __forceinline__ void ffma2(unsigned long long& d,
                                      unsigned long long a, unsigned long long b) {
    asm("fma.rn.f32x2 %0, %1, %2, %0;" : "+l"(d) : "l"(a), "l"(b));
}
__device__ __forceinline__ float2 upk2(unsigned long long v) {
    float2 r;
    asm("mov.b64 {%0,%1}, %2;" : "=f"(r.x), "=f"(r.y) : "l"(v));
    return r;
}
__device__ __forceinline__ void subbar(int nb) {
    asm volatile("bar.sync %0, %1;" :: "r"(nb), "r"(128) : "memory");
}

// ===========================================================================
// BIG GEMM: 128x64 tile, 128 threads, 8x8 microtile, double-buffered,
// conflict-free duplicated-B layout (8 groups x 20-float slots).
// ===========================================================================
enum { B_V = 0, B_WV = 1, B_GXB = 2, B_FINAL = 3 };

template<int MODE>
__global__ __launch_bounds__(128)
void sgemm_big(const float* __restrict__ A,
               const float* __restrict__ Bm,
               const float* __restrict__ bias,
               float* __restrict__ Cout,
               int N, int K)
{
    __shared__ __align__(16) float As [2][16][132];
    __shared__ __align__(16) float Bsd[2][16][164];

    const int tid = threadIdx.x;
    const int n0  = blockIdx.x * 64;
    const int m0  = blockIdx.y * 128;

    int nact = 0;
    if (MODE == B_FINAL) { nact = g_nact; if (m0 >= nact) return; }
    if (MODE == B_GXB)   { Bm = g_Wpack; bias = g_bpack; }
    const int ldb = (MODE == B_GXB) ? 1536 : ((MODE == B_V) ? ENCD : HD);

    const float* arow [4];
    const float* arow2[4];
    int rowi[4], kci[4];
    #pragma unroll
    for (int it = 0; it < 4; it++) {
        int s   = tid + it * 128;
        int row = s >> 2;
        rowi[it] = row;
        kci [it] = (s & 3) << 2;
        int gm = m0 + row;
        if (MODE == B_V) {
            int gr = g_sortind[gm / PP] * PP + gm % PP;
            arow[it] = A + (size_t)gr * ENCD;
        } else if (MODE == B_WV) {
            arow[it] = g_V + (size_t)gm * HD;
        } else if (MODE == B_FINAL) {
            arow[it] = g_CH + (size_t)g_rowmap[gm] * HD;
        } else {
            int b  = gm / NSTEP;
            int ts = gm - b * NSTEP;
            arow [it] = A + (size_t)g_capss[b * TT + ts] * HD;
            arow2[it] = g_vg + (size_t)b * HD;
        }
    }
    const float* brow[2];
    int bc[2], bkci[2];
    bool bok[2];
    #pragma unroll
    for (int it = 0; it < 2; it++) {
        int s  = tid + it * 128;
        int c  = s >> 2;
        bc  [it] = c;
        bkci[it] = (s & 3) << 2;
        int gn = n0 + c;
        bok [it] = (gn < N);
        brow[it] = Bm + (size_t)(bok[it] ? gn : 0) * ldb;
    }

    float4 aR[4], bR[2];

    #define BLOAD_TILE(k0)                                                    \
        {                                                                     \
            _Pragma("unroll")                                                 \
            for (int it = 0; it < 4; it++) {                                  \
                int gk = (k0) + kci[it];                                      \
                if (MODE == B_GXB) {                                          \
                    aR[it] = (gk < HD) ? *(const float4*)&arow[it][gk]        \
                                       : *(const float4*)&arow2[it][gk - HD]; \
                } else {                                                      \
                    aR[it] = *(const float4*)&arow[it][gk];                   \
                }                                                             \
            }                                                                 \
            _Pragma("unroll")                                                 \
            for (int it = 0; it < 2; it++) {                                  \
                bR[it] = bok[it] ? *(const float4*)&brow[it][(k0) + bkci[it]] \
                                 : make_float4(0.f, 0.f, 0.f, 0.f);           \
            }                                                                 \
        }

    #define BSTORE_TILE(buf)                                                  \
        {                                                                     \
            _Pragma("unroll")                                                 \
            for (int it = 0; it < 4; it++) {                                  \
                int kc = kci[it], row = rowi[it];                             \
                As[buf][kc + 0][row] = aR[it].x;                              \
                As[buf][kc + 1][row] = aR[it].y;                              \
                As[buf][kc + 2][row] = aR[it].z;                              \
                As[buf][kc + 3][row] = aR[it].w;                              \
            }                                                                 \
            _Pragma("unroll")                                                 \
            for (int it = 0; it < 2; it++) {                                  \
                int kc = bkci[it];                                            \
                int go = (bc[it] >> 3) * 20 + (bc[it] & 7) * 2;               \
                *(float2*)&Bsd[buf][kc + 0][go] = make_float2(bR[it].x, bR[it].x); \
                *(float2*)&Bsd[buf][kc + 1][go] = make_float2(bR[it].y, bR[it].y); \
                *(float2*)&Bsd[buf][kc + 2][go] = make_float2(bR[it].z, bR[it].z); \
                *(float2*)&Bsd[buf][kc + 3][go] = make_float2(bR[it].w, bR[it].w); \
            }                                                                 \
        }

    #define BLDFRAG(buf, k, aA, aB, b0, b1, b2, b3)                           \
        {                                                                     \
            const ulonglong2* ap = (const ulonglong2*)&As[buf][k][ty << 3];   \
            aA = ap[0]; aB = ap[1];                                           \
            const float* bbase = &Bsd[buf][k][tx * 20];                       \
            b0 = *(const ulonglong2*)(bbase + 0);                             \
            b1 = *(const ulonglong2*)(bbase + 4);                             \
            b2 = *(const ulonglong2*)(bbase + 8);                             \
            b3 = *(const ulonglong2*)(bbase + 12);                            \
        }

    unsigned long long acc[4][8];
    #pragma unroll
    for (int i = 0; i < 4; i++)
        #pragma unroll
        for (int j = 0; j < 8; j++) acc[i][j] = 0ull;

    const int ty = tid >> 3;
    const int tx = tid & 7;

    BLOAD_TILE(0);
    BSTORE_TILE(0);
    __syncthreads();
    int buf = 0;
    const int KT = K >> 4;
    for (int kt = 0; kt < KT; kt++) {
        if (kt + 1 < KT) BLOAD_TILE((kt + 1) << 4);
        ulonglong2 aAc, aBc, aAn, aBn;
        ulonglong2 b0c, b1c, b2c, b3c, b0n, b1n, b2n, b3n;
        BLDFRAG(buf, 0, aAc, aBc, b0c, b1c, b2c, b3c);
        #pragma unroll
        for (int k = 0; k < 16; k++) {
            if (k < 15) BLDFRAG(buf, k + 1, aAn, aBn, b0n, b1n, b2n, b3n);
            ffma2(acc[0][0], aAc.x, b0c.x); ffma2(acc[0][1], aAc.x, b0c.y);
            ffma2(acc[0][2], aAc.x, b1c.x); ffma2(acc[0][3], aAc.x, b1c.y);
            ffma2(acc[0][4], aAc.x, b2c.x); ffma2(acc[0][5], aAc.x, b2c.y);
            ffma2(acc[0][6], aAc.x, b3c.x); ffma2(acc[0][7], aAc.x, b3c.y);
            ffma2(acc[1][0], aAc.y, b0c.x); ffma2(acc[1][1], aAc.y, b0c.y);
            ffma2(acc[1][2], aAc.y, b1c.x); ffma2(acc[1][3], aAc.y, b1c.y);
            ffma2(acc[1][4], aAc.y, b2c.x); ffma2(acc[1][5], aAc.y, b2c.y);
            ffma2(acc[1][6], aAc.y, b3c.x); ffma2(acc[1][7], aAc.y, b3c.y);
            ffma2(acc[2][0], aBc.x, b0c.x); ffma2(acc[2][1], aBc.x, b0c.y);
            ffma2(acc[2][2], aBc.x, b1c.x); ffma2(acc[2][3], aBc.x, b1c.y);
            ffma2(acc[2][4], aBc.x, b2c.x); ffma2(acc[2][5], aBc.x, b2c.y);
            ffma2(acc[2][6], aBc.x, b3c.x); ffma2(acc[2][7], aBc.x, b3c.y);
            ffma2(acc[3][0], aBc.y, b0c.x); ffma2(acc[3][1], aBc.y, b0c.y);
            ffma2(acc[3][2], aBc.y, b1c.x); ffma2(acc[3][3], aBc.y, b1c.y);
            ffma2(acc[3][4], aBc.y, b2c.x); ffma2(acc[3][5], aBc.y, b2c.y);
            ffma2(acc[3][6], aBc.y, b3c.x); ffma2(acc[3][7], aBc.y, b3c.y);
            if (k < 15) {
                aAc = aAn; aBc = aBn;
                b0c = b0n; b1c = b1n; b2c = b2n; b3c = b3n;
            }
        }
        if (kt + 1 < KT) {
            BSTORE_TILE(buf ^ 1);
            __syncthreads();
            buf ^= 1;
        }
    }
    #undef BLOAD_TILE
    #undef BSTORE_TILE
    #undef BLDFRAG

    float* Cp;
    int ldc;
    if      (MODE == B_V)   { Cp = g_V;  ldc = HD; }
    else if (MODE == B_WV)  { Cp = g_WV; ldc = HD; }
    else if (MODE == B_GXB) { Cp = g_GX; ldc = 2560; }
    else                    { Cp = Cout; ldc = N; }

    const int nb = n0 + (tx << 3);
    float bs[8];
    #pragma unroll
    for (int j = 0; j < 8; j++)
        bs[j] = (nb + j < N) ? bias[nb + j] : 0.f;

    #pragma unroll
    for (int i = 0; i < 4; i++) {
        #pragma unroll
        for (int half = 0; half < 2; half++) {
            int r  = (ty << 3) + (i << 1) + half;
            int i0 = m0 + r;
            float vals[8];
            #pragma unroll
            for (int j = 0; j < 8; j++) {
                float2 v = upk2(acc[i][j]);
                float x = (half ? v.y : v.x) + bs[j];
                if (MODE == B_V) x = fmaxf(x, 0.f);
                vals[j] = x;
            }
            if (MODE == B_FINAL) {
                if (i0 < nact) {
                    int rm = g_rowmap[i0];
                    int b = rm & 127, ts = rm >> 7;
                    float* dst = Cp + ((size_t)(b * NSTEP + ts)) * N + nb;
                    if (nb + 7 < N) {
                        *(float4*)(dst)     = make_float4(vals[0], vals[1], vals[2], vals[3]);
                        *(float4*)(dst + 4) = make_float4(vals[4], vals[5], vals[6], vals[7]);
                    } else {
                        #pragma unroll
                        for (int j = 0; j < 8; j++)
                            if (nb + j < N) dst[j] = vals[j];
                    }
                }
            } else {
                float* dst = Cp + (size_t)i0 * ldc + nb;
                *(float4*)(dst)     = make_float4(vals[0], vals[1], vals[2], vals[3]);
                *(float4*)(dst + 4) = make_float4(vals[4], vals[5], vals[6], vals[7]);
            }
        }
    }
}

// ===========================================================================
// SMALL GEMM (split-K, 64x64, 8x4 microtile) — vg + HS launches
// ===========================================================================
enum { MODE_VG = 0, MODE_HS = 3 };

template<int MODE, int KSPLIT>
__global__ __launch_bounds__(128)
void sgemm_nt(const float* __restrict__ A,
              const float* __restrict__ Bm,
              const float* __restrict__ B2,
              int N, int K, int t)
{
    __shared__ __align__(16) float As [2][16][68];
    __shared__ __align__(16) float Bsd[2][16][132];

    const int tid = threadIdx.x;
    const int n0  = blockIdx.x * 64;
    const int m0C = blockIdx.y * 64;
    const int kz  = blockIdx.z;
    int m0A = m0C;

    if (MODE == MODE_HS) {
        if (m0C >= 128) { Bm = B2; m0A = m0C - 128; }
        if (m0A >= g_cnt[t]) return;
    }

    const int ldb = (MODE == MODE_VG) ? ENCD : HD;

    const float* arow[2];
    int rowi[2], kci[2];
    #pragma unroll
    for (int it = 0; it < 2; it++) {
        int s   = tid + it * 128;
        int row = s >> 2;
        rowi[it] = row;
        kci [it] = (s & 3) << 2;
        int gm  = m0A + row;
        if (MODE == MODE_VG) {
            arow[it] = A + (size_t)g_sortind[gm] * ENCD + kz * K;
        } else {
            arow[it] = ((m0C >= 128) ? g_S : g_HN) + (size_t)gm * HD + kz * K;
        }
    }
    const float* brow[2];
    int bn[2], bkci[2];
    #pragma unroll
    for (int it = 0; it < 2; it++) {
        int s  = tid + it * 128;
        int nr = s >> 2;
        bn  [it] = nr;
        bkci[it] = (s & 3) << 2;
        brow[it] = Bm + (size_t)(n0 + nr) * ldb + kz * K;
    }

    float4 aR[2], bR[2];

    #define LOAD_TILE(k0)                                                     \
        {                                                                     \
            _Pragma("unroll")                                                 \
            for (int it = 0; it < 2; it++) {                                  \
                aR[it] = *(const float4*)&arow[it][(k0) + kci[it]];           \
                bR[it] = *(const float4*)&brow[it][(k0) + bkci[it]];          \
            }                                                                 \
        }

    #define STORE_TILE(buf)                                                   \
        {                                                                     \
            _Pragma("unroll")                                                 \
            for (int it = 0; it < 2; it++) {                                  \
                int kc = kci[it], row = rowi[it];                             \
                As[buf][kc + 0][row] = aR[it].x;                              \
                As[buf][kc + 1][row] = aR[it].y;                              \
                As[buf][kc + 2][row] = aR[it].z;                              \
                As[buf][kc + 3][row] = aR[it].w;                              \
            }                                                                 \
            _Pragma("unroll")                                                 \
            for (int it = 0; it < 2; it++) {                                  \
                int kc = bkci[it], nr2 = bn[it] * 2;                          \
                *(float2*)&Bsd[buf][kc + 0][nr2] = make_float2(bR[it].x, bR[it].x); \
                *(float2*)&Bsd[buf][kc + 1][nr2] = make_float2(bR[it].y, bR[it].y); \
                *(float2*)&Bsd[buf][kc + 2][nr2] = make_float2(bR[it].z, bR[it].z); \
                *(float2*)&Bsd[buf][kc + 3][nr2] = make_float2(bR[it].w, bR[it].w); \
            }                                                                 \
        }

    #define LDFRAG(buf, k, aA, aB, b01, b23)                                  \
        {                                                                     \
            const ulonglong2* ap = (const ulonglong2*)&As[buf][k][ty << 3];   \
            aA = ap[0]; aB = ap[1];                                           \
            const ulonglong2* bp = (const ulonglong2*)&Bsd[buf][k][tx << 3];  \
            b01 = bp[0]; b23 = bp[1];                                         \
        }

    unsigned long long acc[4][4];
    #pragma unroll
    for (int i = 0; i < 4; i++)
        #pragma unroll
        for (int j = 0; j < 4; j++) acc[i][j] = 0ull;

    const int ty = tid >> 4;
    const int tx = tid & 15;

    LOAD_TILE(0);
    STORE_TILE(0);
    __syncthreads();
    int buf = 0;
    const int KT = K >> 4;
    for (int kt = 0; kt < KT; kt++) {
        if (kt + 1 < KT) LOAD_TILE((kt + 1) << 4);
        ulonglong2 aAc, aBc, b01c, b23c, aAn, aBn, b01n, b23n;
        LDFRAG(buf, 0, aAc, aBc, b01c, b23c);
        #pragma unroll
        for (int k = 0; k < 16; k++) {
            if (k < 15) LDFRAG(buf, k + 1, aAn, aBn, b01n, b23n);
            ffma2(acc[0][0], aAc.x, b01c.x); ffma2(acc[0][1], aAc.x, b01c.y);
            ffma2(acc[0][2], aAc.x, b23c.x); ffma2(acc[0][3], aAc.x, b23c.y);
            ffma2(acc[1][0], aAc.y, b01c.x); ffma2(acc[1][1], aAc.y, b01c.y);
            ffma2(acc[1][2], aAc.y, b23c.x); ffma2(acc[1][3], aAc.y, b23c.y);
            ffma2(acc[2][0], aBc.x, b01c.x); ffma2(acc[2][1], aBc.x, b01c.y);
            ffma2(acc[2][2], aBc.x, b23c.x); ffma2(acc[2][3], aBc.x, b23c.y);
            ffma2(acc[3][0], aBc.y, b01c.x); ffma2(acc[3][1], aBc.y, b01c.y);
            ffma2(acc[3][2], aBc.y, b23c.x); ffma2(acc[3][3], aBc.y, b23c.y);
            if (k < 15) { aAc = aAn; aBc = aBn; b01c = b01n; b23c = b23n; }
        }
        if (kt + 1 < KT) {
            STORE_TILE(buf ^ 1);
            __syncthreads();
            buf ^= 1;
        }
    }
    #undef LOAD_TILE
    #undef STORE_TILE
    #undef LDFRAG

    float* Cp;
    int ldc;
    if (MODE == MODE_HS) { Cp = g_WhWsP + (size_t)kz * (2 * BB * HD); ldc = HD; }
    else                 { Cp = g_vgP   + (size_t)kz * (BB * HD);     ldc = HD; }

    #pragma unroll
    for (int j = 0; j < 4; j++) {
        int n = n0 + (tx << 2) + j;
        #pragma unroll
        for (int i2 = 0; i2 < 4; i2++) {
            float2 v = upk2(acc[i2][j]);
            int r0 = (ty << 3) + (i2 << 1);
            Cp[(size_t)(m0C + r0)     * ldc + n] = v.x;
            Cp[(size_t)(m0C + r0 + 1) * ldc + n] = v.y;
        }
    }
}

// ===========================================================================
// gemm64: 64x64xK tile, 128 threads (one sub-block), raw partial store.
// (Proven in R15.)
// ===========================================================================
__device__ void gemm64(int t128, int nbar,
                       const float* __restrict__ Abase, int lda,
                       const float* __restrict__ Bbase, int ldb, int K,
                       float* __restrict__ Cbase, int ldc,
                       float (*As)[16][68], float (*Bs)[16][132])
{
    const float* arow[2];
    const float* brow[2];
    int rowi[2], kci[2];
    #pragma unroll
    for (int it = 0; it < 2; it++) {
        int s   = t128 + it * 128;
        int row = s >> 2;
        rowi[it] = row;
        kci [it] = (s & 3) << 2;
        arow[it] = Abase + (size_t)row * lda;
        brow[it] = Bbase + (size_t)row * ldb;
    }
    float4 aR[2], bR[2];

    #define PLOAD(k0)                                                         \
        {                                                                     \
            _Pragma("unroll")                                                 \
            for (int it = 0; it < 2; it++) {                                  \
                aR[it] = *(const float4*)&arow[it][(k0) + kci[it]];           \
                bR[it] = *(const float4*)&brow[it][(k0) + kci[it]];           \
            }                                                                 \
        }
    #define PSTORE(buf)                                                       \
        {                                                                     \
            _Pragma("unroll")                                                 \
            for (int it = 0; it < 2; it++) {                                  \
                int kc = kci[it], row = rowi[it];                             \
                As[buf][kc + 0][row] = aR[it].x;                              \
                As[buf][kc + 1][row] = aR[it].y;                              \
                As[buf][kc + 2][row] = aR[it].z;                              \
                As[buf][kc + 3][row] = aR[it].w;                              \
                int nr2 = row * 2;                                            \
                *(float2*)&Bs[buf][kc + 0][nr2] = make_float2(bR[it].x, bR[it].x); \
                *(float2*)&Bs[buf][kc + 1][nr2] = make_float2(bR[it].y, bR[it].y); \
                *(float2*)&Bs[buf][kc + 2][nr2] = make_float2(bR[it].z, bR[it].z); \
                *(float2*)&Bs[buf][kc + 3][nr2] = make_float2(bR[it].w, bR[it].w); \
            }                                                                 \
        }
    #define PFRAG(buf, k, aA, aB, b01, b23)                                   \
        {                                                                     \
            const ulonglong2* ap = (const ulonglong2*)&As[buf][k][ty << 3];   \
            aA = ap[0]; aB = ap[1];                                           \
            const ulonglong2* bp = (const ulonglong2*)&Bs[buf][k][tx << 3];   \
            b01 = bp[0]; b23 = bp[1];                                         \
        }

    unsigned long long acc[4][4];
    #pragma unroll
    for (int i = 0; i < 4; i++)
        #pragma unroll
        for (int j = 0; j < 4; j++) acc[i][j] = 0ull;

    const int ty = t128 >> 4;
    const int tx = t128 & 15;

    PLOAD(0);
    PSTORE(0);
    subbar(nbar);
    int buf = 0;
    const int KT = K >> 4;
    for (int kt = 0; kt < KT; kt++) {
        if (kt + 1 < KT) PLOAD((kt + 1) << 4);
        ulonglong2 aAc, aBc, b01c, b23c, aAn, aBn, b01n, b23n;
        PFRAG(buf, 0, aAc, aBc, b01c, b23c);
        #pragma unroll
        for (int k = 0; k < 16; k++) {
            if (k < 15) PFRAG(buf, k + 1, aAn, aBn, b01n, b23n);
            ffma2(acc[0][0], aAc.x, b01c.x); ffma2(acc[0][1], aAc.x, b01c.y);
            ffma2(acc[0][2], aAc.x, b23c.x); ffma2(acc[0][3], aAc.x, b23c.y);
            ffma2(acc[1][0], aAc.y, b01c.x); ffma2(acc[1][1], aAc.y, b01c.y);
            ffma2(acc[1][2], aAc.y, b23c.x); ffma2(acc[1][3], aAc.y, b23c.y);
            ffma2(acc[2][0], aBc.x, b01c.x); ffma2(acc[2][1], aBc.x, b01c.y);
            ffma2(acc[2][2], aBc.x, b23c.x); ffma2(acc[2][3], aBc.x, b23c.y);
            ffma2(acc[3][0], aBc.y, b01c.x); ffma2(acc[3][1], aBc.y, b01c.y);
            ffma2(acc[3][2], aBc.y, b23c.x); ffma2(acc[3][3], aBc.y, b23c.y);
            if (k < 15) { aAc = aAn; aBc = aBn; b01c = b01n; b23c = b23n; }
        }
        if (kt + 1 < KT) {
            PSTORE(buf ^ 1);
            subbar(nbar);
            buf ^= 1;
        }
    }
    #undef PLOAD
    #undef PSTORE
    #undef PFRAG

    #pragma unroll
    for (int j = 0; j < 4; j++) {
        int n = (tx << 2) + j;
        #pragma unroll
        for (int i2 = 0; i2 < 4; i2++) {
            float2 v = upk2(acc[i2][j]);
            int r0 = (ty << 3) + (i2 << 1);
            Cbase[(size_t)r0       * ldc + n] = v.x;
            Cbase[(size_t)(r0 + 1) * ldc + n] = v.y;
        }
    }
}

__device__ __forceinline__ float sigm(float x) { return 1.0f / (1.0f + expf(-x)); }

// ===========================================================================
// K1: fused [ attention(t_attn)  ||  gates-GEMM partials(t_g) ]
// Blocks 0..127: attention (256 threads, one b per block).
// Blocks 128.. : gates GEMM, two 64x64 sub-jobs per block (named barriers).
// ===========================================================================
__global__ __launch_bounds__(256)
void k1_fused(int t_attn, int t_g, int do_attn, int do_g,
              const float* __restrict__ attbh, const float* __restrict__ attbs,
              const float* __restrict__ wa,    const float* __restrict__ ba,
              const float* __restrict__ wahat, const float* __restrict__ bahat)
{
    __shared__ __align__(16) float As[2][2][16][68];
    __shared__ __align__(16) float Bs[2][2][16][132];

    const int bid = blockIdx.x;
    const int tid = threadIdx.x;

    if (bid < 128) {
        // ---------------- attention for batch row b at step t_attn ----------
        if (!do_attn) return;
        int b = bid;
        if (b >= g_cnt[t_attn]) return;
        float* sm   = (float*)As;        // 4352 floats available
        float* shWh = sm;
        float* shWs = sm + 512;
        float* zsh  = sm + 1024;
        float* alph = sm + 1088;

        for (int e = tid; e < 512; e += 256) {
            float vh = attbh[e], vs = attbs[e];
            #pragma unroll
            for (int z = 0; z < KS_HS; z++) {
                vh += g_WhWsP[(size_t)z * (2 * BB * HD) + (size_t)b * HD + e];
                vs += g_WhWsP[(size_t)z * (2 * BB * HD) + (size_t)(BB + b) * HD + e];
            }
            shWh[e] = vh;
            shWs[e] = vs;
        }
        __syncthreads();

        int warp = tid >> 5, lane = tid & 31;
        for (int idx = warp; idx < 50; idx += 8) {
            float sum = 0.f;
            if (idx < 49) {
                const float* wv = g_WV + ((size_t)(b * PP + idx)) * 512;
                #pragma unroll
                for (int e = lane; e < 512; e += 32)
                    sum += tanhf(wv[e] + shWh[e]) * wa[e];
            } else {
                #pragma unroll
                for (int e = lane; e < 512; e += 32)
                    sum += tanhf(shWs[e] + shWh[e]) * wahat[e];
            }
            #pragma unroll
            for (int o = 16; o; o >>= 1) sum += __shfl_down_sync(0xffffffffu, sum, o);
            if (lane == 0) zsh[idx] = sum + (idx < 49 ? ba[0] : bahat[0]);
        }
        __syncthreads();

        if (warp == 0) {
            float z0 = (lane < 49)      ? zsh[lane]      : -1e30f;
            float z1 = (lane + 32 < 49) ? zsh[lane + 32] : -1e30f;
            float mx = fmaxf(z0, z1);
            #pragma unroll
            for (int o = 16; o; o >>= 1) mx = fmaxf(mx, __shfl_xor_sync(0xffffffffu, mx, o));
            float e0 = (lane < 49)      ? expf(z0 - mx) : 0.f;
            float e1 = (lane + 32 < 49) ? expf(z1 - mx) : 0.f;
            float smx = e0 + e1;
            #pragma unroll
            for (int o = 16; o; o >>= 1) smx += __shfl_xor_sync(0xffffffffu, smx, o);
            float inv = 1.f / smx;
            if (lane < 49)      alph[lane]      = e0 * inv;
            if (lane + 32 < 49) alph[lane + 32] = e1 * inv;
            if (lane == 0) {
                float zh = zsh[49];
                float m2 = fmaxf(mx, zh);
                float s2 = smx * expf(mx - m2) + expf(zh - m2);
                sm[1153] = expf(zh - m2) / s2;
            }
        }
        __syncthreads();

        float beta = sm[1153];
        for (int e = tid; e < 512; e += 256) {
            float c = 0.f;
            const float* Vb = g_V + (size_t)b * PP * 512 + e;
            #pragma unroll 7
            for (int p = 0; p < PP; p++) c += alph[p] * Vb[p * 512];
            int idx = b * 512 + e;
            float ch = beta * g_S[idx] + (1.f - beta) * c + g_HN[idx];
            g_CH[((size_t)t_attn * BB + b) * 512 + e] = ch;
        }
    } else {
        // ---------------- gates GEMM partials for step t_g -------------------
        if (!do_g) return;
        const int sub  = tid >> 7;
        const int t128 = tid & 127;
        const int nbar = sub + 1;
        int j = (bid - 128) * 2 + sub;           // 0..319
        if (j >= 40 * 2 * KS_G) return;
        int ntile = j % 40;
        int r     = j / 40;
        int mtile = r & 1;
        int kz    = r >> 1;
        if (mtile * 64 >= g_cnt[t_g]) return;
        gemm64(t128, nbar,
               g_H + (size_t)(mtile * 64) * HD + kz * 128, HD,
               g_Wpack + 1024 + (size_t)(ntile * 64) * 1536 + kz * 128, 1536,
               128,
               g_Gp + (size_t)kz * (BB * 2560)
                    + (size_t)(mtile * 64) * 2560 + ntile * 64, 2560,
               As[sub], Bs[sub]);
    }
}

// ---------------------------------------------------------------------------
// Prep: stable descending argsort, caps gather, cnt_t, compact rowmap, tails
// ---------------------------------------------------------------------------
__global__ void prep_kernel(const int* __restrict__ caplens,
                            const int* __restrict__ caps,
                            float* __restrict__ out, long long out_size)
{
    __shared__ int clsh[BB];
    __shared__ int off[NSTEP + 1];
    int b = threadIdx.x;
    int cl = caplens[b];
    clsh[b] = cl;
    __syncthreads();
    int rank = 0;
    #pragma unroll 8
    for (int j = 0; j < BB; j++) {
        int cj = clsh[j];
        if (cj > cl || (cj == cl && j < b)) rank++;
    }
    g_sortind[rank] = b;
    g_declen[rank]  = cl - 1;
    __syncthreads();

    int si = g_sortind[b];
    for (int t = 0; t < TT; t++) g_capss[b * TT + t] = caps[si * TT + t];

    if (b < NSTEP) {
        int c = 0;
        for (int j = 0; j < BB; j++) if (g_declen[j] > b) c++;
        g_cnt[b] = c;
    }
    __syncthreads();
    if (b == 0) {
        int o = 0;
        for (int t = 0; t < NSTEP; t++) { off[t] = o; o += g_cnt[t]; }
        off[NSTEP] = o;
        g_nact = o;
    }
    __syncthreads();
    for (int t = 0; t < NSTEP; t++)
        if (b < g_cnt[t]) g_rowmap[off[t] + b] = t * BB + b;
    __syncthreads();
    int nact = off[NSTEP];
    int lastrm = g_rowmap[nact - 1];
    for (int i = nact + b; i < MACT_PAD; i += BB) g_rowmap[i] = lastrm;

    for (int i = b; i < BB * HD; i += BB) { g_H[i] = 0.f; g_M[i] = 0.f; }

    if (out_size >= PRED_ELEMS + 2816LL) {
        for (int t = 0; t < TT; t++)
            out[PRED_ELEMS + b * TT + t] = (float)g_capss[b * TT + t];
        out[PRED_ELEMS + 2560 + b] = (float)g_declen[b];
        out[PRED_ELEMS + 2688 + b] = (float)g_sortind[b];
    }
}

// ---------------------------------------------------------------------------
// Pack LSTM + gate weights into one (2560 x 1536) NT weight + fused bias
// ---------------------------------------------------------------------------
__global__ void pack_weights(const float* __restrict__ Wih, const float* __restrict__ Whh,
                             const float* __restrict__ Wx,  const float* __restrict__ Wph,
                             const float* __restrict__ bih, const float* __restrict__ bhh,
                             const float* __restrict__ bx,  const float* __restrict__ bph)
{
    int i = blockIdx.x * blockDim.x + threadIdx.x;
    int n = i / 1536;
    int k = i - n * 1536;
    float v;
    if (n < 2048) v = (k < 1024) ? Wih[n * 1024 + k] : Whh[n * 512 + (k - 1024)];
    else {
        int n2 = n - 2048;
        v = (k < 1024) ? Wx[n2 * 1024 + k] : Wph[n2 * 512 + (k - 1024)];
    }
    g_Wpack[i] = v;
    if (i < 2560)
        g_bpack[i] = (i < 2048) ? (bih[i] + bhh[i]) : (bx[i - 2048] + bph[i - 2048]);
}

// ---------------------------------------------------------------------------
// vg split-K reduction + bias + relu
// ---------------------------------------------------------------------------
__global__ void vg_reduce(const float* __restrict__ bg)
{
    int i = blockIdx.x * 256 + threadIdx.x;
    float v = bg[i & 511];
    #pragma unroll
    for (int z = 0; z < KS_VG; z++) v += g_vgP[z * (BB * HD) + i];
    g_vg[i] = fmaxf(v, 0.f);
}

// ---------------------------------------------------------------------------
// Zero-fill predictions of inactive (b,t) rows
// ---------------------------------------------------------------------------
__global__ void zero_inactive(float* __restrict__ out)
{
    int bt = blockIdx.x;
    int b = bt / NSTEP, t = bt - b * NSTEP;
    if (t < g_declen[b]) return;
    float4* dst = (float4*)(out + (size_t)bt * VOC);
    for (int i = threadIdx.x; i < VOC / 4; i += blockDim.x)
        dst[i] = make_float4(0.f, 0.f, 0.f, 0.f);
}

// ---------------------------------------------------------------------------
// LSTM elementwise (active rows only): sums split-K partials + GX
// ---------------------------------------------------------------------------
__global__ void lstm_ew(int t)
{
    if ((int)(blockIdx.x >> 1) >= g_cnt[t]) return;
    int idx = blockIdx.x * 256 + threadIdx.x;
    int b = idx >> 9, j = idx & 511;
    const float* GX = g_GX + ((size_t)b * NSTEP + t) * 2560;
    float ga[5];
    #pragma unroll
    for (int g5 = 0; g5 < 5; g5++) {
        int n = g5 * 512 + j;
        float v = GX[n];
        #pragma unroll
        for (int z = 0; z < KS_G; z++)
            v += g_Gp[(size_t)z * (BB * 2560) + (size_t)b * 2560 + n];
        ga[g5] = v;
    }
    float ig = sigm(ga[0]);
    float fg = sigm(ga[1]);
    float gg = tanhf(ga[2]);
    float og = sigm(ga[3]);
    float gt = sigm(ga[4]);
    float mn = fg * g_M[idx] + ig * gg;
    float tm = tanhf(mn);
    float hn = og * tm;
    g_HN[idx] = hn;
    g_S[idx]  = gt * tm;
    if (t < g_declen[b]) { g_H[idx] = hn; g_M[idx] = mn; }
}

// ---------------------------------------------------------------------------
// Host launcher — kernel launches only
// ---------------------------------------------------------------------------
extern "C" void kernel_launch(void* const* d_in, const int* in_sizes, int n_in,
                              void* d_out, int out_size)
{
    (void)in_sizes; (void)n_in;
    const float* enc    = (const float*)d_in[0];
    const float* gimg   = (const float*)d_in[1];
    const int*   caps   = (const int*)  d_in[2];
    const int*   caplens= (const int*)  d_in[3];
    const float* embW   = (const float*)d_in[4];
    const float* Wih    = (const float*)d_in[5];
    const float* Whh    = (const float*)d_in[6];
    const float* bih    = (const float*)d_in[7];
    const float* bhh    = (const float*)d_in[8];
    const float* Wg     = (const float*)d_in[9];
    const float* bg     = (const float*)d_in[10];
    const float* Wi     = (const float*)d_in[11];
    const float* bi     = (const float*)d_in[12];
    const float* Wx     = (const float*)d_in[13];
    const float* bx     = (const float*)d_in[14];
    const float* Wph    = (const float*)d_in[15];
    const float* bph    = (const float*)d_in[16];
    const float* attWh  = (const float*)d_in[17];
    const float* attbh  = (const float*)d_in[18];
    const float* attWs  = (const float*)d_in[19];
    const float* attbs  = (const float*)d_in[20];
    const float* attWV  = (const float*)d_in[21];
    const float* attbV  = (const float*)d_in[22];
    const float* wa     = (const float*)d_in[23];
    const float* ba     = (const float*)d_in[24];
    const float* wahat  = (const float*)d_in[25];
    const float* bahat  = (const float*)d_in[26];
    const float* finalW = (const float*)d_in[27];
    const float* finalb = (const float*)d_in[28];
    float* out = (float*)d_out;

    // --- setup ---
    prep_kernel<<<1, 128>>>(caplens, caps, out, (long long)out_size);
    pack_weights<<<(2560 * 1536) / 256, 256>>>(Wih, Whh, Wx, Wph, bih, bhh, bx, bph);
    zero_inactive<<<BB * NSTEP, 256>>>(out);

    // vg partials (split-K 8) + reduce
    sgemm_nt<MODE_VG, KS_VG><<<dim3(8, 2, KS_VG), 128>>>(gimg, Wg, nullptr,
        HD, ENCD / KS_VG, 0);
    vg_reduce<<<BB * HD / 256, 256>>>(bg);
    // V = relu(enc_s @ Wi^T + bi)
    sgemm_big<B_V><<<dim3(8, MROWS / 128), 128>>>(enc, Wi, bi, nullptr, HD, ENCD);
    // GX = [emb_t | vg] @ Wpack[:, :1024]^T + bpack
    sgemm_big<B_GXB><<<dim3(40, MACT_PAD / 128), 128>>>(embW, nullptr, nullptr,
        nullptr, 2560, 1024);
    // WV = V @ att_WV^T + bV
    sgemm_big<B_WV><<<dim3(8, MROWS / 128), 128>>>(nullptr, attWV, attbV,
        nullptr, HD, HD);

    // --- 19 decode steps: K1 [attn(t-1) || gates(t)] -> lstm(t) -> HS(t) ---
    for (int t = 0; t < NSTEP; t++) {
        k1_fused<<<288, 256>>>(t - 1, t, (t > 0) ? 1 : 0, 1,
                               attbh, attbs, wa, ba, wahat, bahat);
        lstm_ew<<<BB * HD / 256, 256>>>(t);
        sgemm_nt<MODE_HS, KS_HS><<<dim3(8, 4, KS_HS), 128>>>(nullptr, attWh, attWs,
            HD, HD / KS_HS, t);
    }
    // tail attention for t = 18
    k1_fused<<<288, 256>>>(NSTEP - 1, 0, 1, 0,
                           attbh, attbs, wa, ba, wahat, bahat);

    // --- batched final projection over compacted active rows ---
    sgemm_big<B_FINAL><<<dim3((VOC + 63) / 64, MACT_PAD / 128), 128>>>(nullptr,
        finalW, finalb, out, VOC, HD);
}